// round 12
// baseline (speedup 1.0000x reference)
#include <cuda_runtime.h>

namespace {

constexpr int Bn = 2, Cin = 128, Co = 128, Hh = 128, Ww = 256;
constexpr int HW = Hh * Ww;
constexpr int KK = 9;
constexpr int Cmid = 32;
constexpr int TP = 32;          // pixels per block tile
constexpr int CC = 4;           // input channels per chunk
constexpr int NK = CC * KK;     // 36 (ci,k) pairs per chunk
constexpr int NCH = Cin / CC;   // 32 chunks
constexpr int NP = KK * TP;     // 288 (k,p) pairs
constexpr int NR = 11;          // tile rows  (y-5 .. y+5)
constexpr int NC = 44;          // tile cols  (x0-5 .. x0+38)
constexpr int CPT = NR * NC;    // 484 floats per channel tile

typedef unsigned long long ull;

__device__ __forceinline__ ull ffma2(ull a, ull b, ull c) {
  ull d;
  asm("fma.rn.f32x2 %0, %1, %2, %3;" : "=l"(d) : "l"(a), "l"(b), "l"(c));
  return d;
}
__device__ __forceinline__ ull pack2(float lo, float hi) {
  ull r;
  asm("mov.b64 %0, {%1, %2};" : "=l"(r) : "f"(lo), "f"(hi));
  return r;
}
__device__ __forceinline__ float2 unpack2(ull v) {
  float2 r;
  asm("mov.b64 {%0, %1}, %2;" : "=f"(r.x), "=f"(r.y) : "l"(v));
  return r;
}

struct SmemP1 {
  float wsm[NK][Co];   // 18432 B  weight slice, [cci*9+k][co]
  float sA[NK][TP];    //  4608 B  static conv column
  float sD[NK][TP];    //  4608 B  deformable column
};
struct SmemP2 {
  float hs[Co][TP];    // 16384 B  h (with bias)
  float ds[Co][TP];    // 16384 B  dx (with bias)
};
struct __align__(16) Smem {
  union { SmemP1 p1; SmemP2 p2; } u;          // 32768 B (offset 0)
  short4 scxy[NP];                             //  2304 B clamped corner coords
  float4 smw[NP];                              //  4608 B corner weights (validity folded)
  union {
    float tile[CC][NR][NC];                    //  7744 B gather tile (per chunk)
    float los[Cmid][TP];                       //  4096 B LoRA mid (epilogue only)
  } t;
};                                             // total 47424 B < 48KB

}  // namespace

__global__ void __launch_bounds__(128, 4)
fused_dcn_lora(const float* __restrict__ x, const float* __restrict__ offs,
               const float* __restrict__ weight, const float* __restrict__ bias,
               const float* __restrict__ down_w, const float* __restrict__ up_w,
               const float* __restrict__ scale_p, float* __restrict__ out)
{
  __shared__ Smem s;
  const int tid = threadIdx.x;
  const int x0 = blockIdx.x * TP;
  const int y  = blockIdx.y;
  const int b  = blockIdx.z;
  const int cg = tid >> 2;    // 0..31  -> co0 = cg*4
  const int pg = tid & 3;     // 0..3   -> p0  = pg*8
  const int co0 = cg * 4;
  const int p0 = pg * 8;

  const int ylo = ::max(0, y - 5),  yhi = ::min(Hh - 1, y + 5);
  const int xlo = ::max(0, x0 - 5), xhi = ::min(Ww - 1, x0 + 38);

  // ---- bilinear metadata per (k, p): clamped corner coords + weights ----
  for (int idx = tid; idx < NP; idx += 128) {
    const int k = idx >> 5, p = idx & 31;
    const int ky = k / 3, kx = k - ky * 3;
    const float dy  = offs[(2 * k)     * HW + y * Ww + x0 + p];
    const float dxo = offs[(2 * k + 1) * HW + y * Ww + x0 + p];
    const float py = (float)(y - 1 + ky) + dy;
    const float px = (float)(x0 + p - 1 + kx) + dxo;
    const float fy0 = floorf(py), fx0 = floorf(px);
    const int iy0 = (int)fy0, ix0 = (int)fx0;
    const int iy1 = iy0 + 1,  ix1 = ix0 + 1;
    const float fy = py - fy0, fx = px - fx0;
    const bool vy0 = (iy0 >= 0) && (iy0 < Hh);
    const bool vy1 = (iy1 >= 0) && (iy1 < Hh);
    const bool vx0 = (ix0 >= 0) && (ix0 < Ww);
    const bool vx1 = (ix1 >= 0) && (ix1 < Ww);
    const int cy0 = ::min(::max(iy0, 0), Hh - 1);
    const int cy1 = ::min(::max(iy1, 0), Hh - 1);
    const int cx0 = ::min(::max(ix0, 0), Ww - 1);
    const int cx1 = ::min(::max(ix1, 0), Ww - 1);
    s.scxy[idx] = make_short4((short)cy0, (short)cy1, (short)cx0, (short)cx1);
    s.smw[idx] = make_float4(
        (vy0 && vx0) ? (1.f - fy) * (1.f - fx) : 0.f,
        (vy0 && vx1) ? (1.f - fy) * fx         : 0.f,
        (vy1 && vx0) ? fy * (1.f - fx)         : 0.f,
        (vy1 && vx1) ? fy * fx                 : 0.f);
  }
  __syncthreads();

  // ---- accumulators: [4 co][4 pixel-pairs] packed f32x2, for h and dx ----
  ull hacc[4][4], dacc[4][4];
#pragma unroll
  for (int i = 0; i < 4; i++)
#pragma unroll
    for (int q = 0; q < 4; q++) { hacc[i][q] = 0ull; dacc[i][q] = 0ull; }

  for (int ch = 0; ch < NCH; ch++) {
    const int ci0 = ch * CC;
    const float* xbase = x + (size_t)(b * Cin + ci0) * HW;

    // phase A: stage weight slice + fill gather tile
    {
      const float4* wg4 = (const float4*)(weight + tid * (Cin * KK) + ci0 * KK);
#pragma unroll
      for (int jq = 0; jq < NK / 4; jq++) {
        const float4 t = wg4[jq];
        s.u.p1.wsm[jq * 4 + 0][tid] = t.x;
        s.u.p1.wsm[jq * 4 + 1][tid] = t.y;
        s.u.p1.wsm[jq * 4 + 2][tid] = t.z;
        s.u.p1.wsm[jq * 4 + 3][tid] = t.w;
      }
    }
    for (int i = tid; i < CC * CPT; i += 128) {
      const int cc = i / CPT;
      const int rem = i - cc * CPT;
      const int r = rem / NC, c = rem - r * NC;
      const int gy = ylo + r, gx = xlo + c;
      if (gy <= yhi && gx <= xhi)
        s.t.tile[cc][r][c] = xbase[cc * HW + gy * Ww + gx];
    }
    __syncthreads();

    // phase B: column staging, pair-major (metadata loaded once per pair)
#pragma unroll
    for (int j = 0; j < 3; j++) {
      int pair, cciBeg, cciEnd;
      if (j < 2) { pair = j * 128 + tid; cciBeg = 0; cciEnd = CC; }
      else       { pair = 256 + (tid >> 2); cciBeg = tid & 3; cciEnd = cciBeg + 1; }
      const int k = pair >> 5, p = pair & 31;
      const int ky = k / 3, kx = k - ky * 3;
      const short4 cc4 = s.scxy[pair];
      const float4 w4 = s.smw[pair];
      const int yy = y + ky - 1, xx = x0 + p + kx - 1;
      const bool sval = (yy >= 0) && (yy < Hh) && (xx >= 0) && (xx < Ww);
      const int soff = (yy - ylo) * NC + (xx - xlo);
      const bool intile = (cc4.x >= ylo) && (cc4.y <= yhi) &&
                          (cc4.z >= xlo) && (cc4.w <= xhi);
      const int r0 = ((int)cc4.x - ylo) * NC, r1 = ((int)cc4.y - ylo) * NC;
      const int c0 = (int)cc4.z - xlo, c1 = (int)cc4.w - xlo;
      const int g00 = (int)cc4.x * Ww + (int)cc4.z;
      const int g01 = (int)cc4.x * Ww + (int)cc4.w;
      const int g10 = (int)cc4.y * Ww + (int)cc4.z;
      const int g11 = (int)cc4.y * Ww + (int)cc4.w;
      for (int cci = cciBeg; cci < cciEnd; cci++) {
        const float* tl = &s.t.tile[cci][0][0];
        const int kci = cci * KK + k;
        s.u.p1.sA[kci][p] = sval ? tl[soff] : 0.f;
        float v00, v01, v10, v11;
        if (intile) {
          v00 = tl[r0 + c0]; v01 = tl[r0 + c1];
          v10 = tl[r1 + c0]; v11 = tl[r1 + c1];
        } else {
          const float* plane = xbase + cci * HW;
          v00 = plane[g00]; v01 = plane[g01];
          v10 = plane[g10]; v11 = plane[g11];
        }
        s.u.p1.sD[kci][p] = w4.x * v00 + w4.y * v01 + w4.z * v10 + w4.w * v11;
      }
    }
    __syncthreads();

    // phase C: MAC loop — per (ci,k): 1 LDS.128 weight, 2 LDS.128 x2 acts, 32 FFMA2
#pragma unroll 6
    for (int kci = 0; kci < NK; kci++) {
      const float4 wv = *(const float4*)(&s.u.p1.wsm[kci][co0]);
      const ulonglong2* aA = (const ulonglong2*)(&s.u.p1.sA[kci][p0]);
      const ulonglong2* aD = (const ulonglong2*)(&s.u.p1.sD[kci][p0]);
      const ulonglong2 A0 = aA[0], A1 = aA[1];
      const ulonglong2 D0 = aD[0], D1 = aD[1];
      const ull a0 = A0.x, a1 = A0.y, a2 = A1.x, a3 = A1.y;
      const ull d0 = D0.x, d1 = D0.y, d2 = D1.x, d3 = D1.y;
#define MACROW(ic, wl) do {                                  \
      const ull wp = pack2((wl), (wl));                      \
      hacc[ic][0] = ffma2(wp, a0, hacc[ic][0]);              \
      hacc[ic][1] = ffma2(wp, a1, hacc[ic][1]);              \
      hacc[ic][2] = ffma2(wp, a2, hacc[ic][2]);              \
      hacc[ic][3] = ffma2(wp, a3, hacc[ic][3]);              \
      dacc[ic][0] = ffma2(wp, d0, dacc[ic][0]);              \
      dacc[ic][1] = ffma2(wp, d1, dacc[ic][1]);              \
      dacc[ic][2] = ffma2(wp, d2, dacc[ic][2]);              \
      dacc[ic][3] = ffma2(wp, d3, dacc[ic][3]);              \
    } while (0)
      MACROW(0, wv.x);
      MACROW(1, wv.y);
      MACROW(2, wv.z);
      MACROW(3, wv.w);
#undef MACROW
    }
    __syncthreads();
  }

  // ---- epilogue: bias, spill h/dx to smem (union overlay) ----
#pragma unroll
  for (int ic = 0; ic < 4; ic++) {
    const float bb = bias[co0 + ic];
#pragma unroll
    for (int q = 0; q < 4; q++) {
      const float2 th = unpack2(hacc[ic][q]);
      const float2 td = unpack2(dacc[ic][q]);
      s.u.p2.hs[co0 + ic][p0 + 2 * q]     = th.x + bb;
      s.u.p2.hs[co0 + ic][p0 + 2 * q + 1] = th.y + bb;
      s.u.p2.ds[co0 + ic][p0 + 2 * q]     = td.x + bb;
      s.u.p2.ds[co0 + ic][p0 + 2 * q + 1] = td.y + bb;
    }
  }
  __syncthreads();

  // ---- LoRA down: lo[m][p] = sum_c down_w[m][c]*dx[c][p] + down_w[m][128+c]*h[c][p]
  {
    const int m = tid >> 2;     // 32 mids x 4 pixel groups == 128 threads
    float lacc[8];
#pragma unroll
    for (int i = 0; i < 8; i++) lacc[i] = 0.f;
    const float* dwm = down_w + m * (2 * Co);
    for (int c = 0; c < Co; c++) {
      const float wd = dwm[c];
      const float wh = dwm[Co + c];
      const float* dr = &s.u.p2.ds[c][p0];
      const float* hr = &s.u.p2.hs[c][p0];
#pragma unroll
      for (int i = 0; i < 8; i++) lacc[i] += wd * dr[i] + wh * hr[i];
    }
#pragma unroll
    for (int i = 0; i < 8; i++) s.t.los[m][p0 + i] = lacc[i];
  }
  __syncthreads();

  // ---- LoRA up + residual + store ----
  const float sc = *scale_p;
#pragma unroll
  for (int ic = 0; ic < 4; ic++) {
    const int co = co0 + ic;
    float up[8];
#pragma unroll
    for (int i = 0; i < 8; i++) up[i] = 0.f;
    const float* uw = up_w + co * Cmid;
#pragma unroll
    for (int mm = 0; mm < Cmid; mm++) {
      const float wv2 = uw[mm];
      const float* lr = &s.t.los[mm][p0];
#pragma unroll
      for (int i = 0; i < 8; i++) up[i] += wv2 * lr[i];
    }
    const float* hr = &s.u.p2.hs[co][p0];
    float* og = out + (((size_t)b * Co + co) * Hh + y) * Ww + x0 + p0;
    float4 o0, o1;
    o0.x = hr[0] + sc * up[0];
    o0.y = hr[1] + sc * up[1];
    o0.z = hr[2] + sc * up[2];
    o0.w = hr[3] + sc * up[3];
    o1.x = hr[4] + sc * up[4];
    o1.y = hr[5] + sc * up[5];
    o1.z = hr[6] + sc * up[6];
    o1.w = hr[7] + sc * up[7];
    *(float4*)og       = o0;
    *(float4*)(og + 4) = o1;
  }
}

extern "C" void kernel_launch(void* const* d_in, const int* in_sizes, int n_in,
                              void* d_out, int out_size) {
  (void)in_sizes; (void)n_in; (void)out_size;
  const float* x      = (const float*)d_in[0];
  const float* offs   = (const float*)d_in[1];
  const float* weight = (const float*)d_in[2];
  const float* bias   = (const float*)d_in[3];
  const float* down_w = (const float*)d_in[4];
  const float* up_w   = (const float*)d_in[5];
  const float* scale  = (const float*)d_in[6];
  dim3 grid(Ww / TP, Hh, Bn);   // 8 x 128 x 2 = 2048 blocks
  fused_dcn_lora<<<grid, 128>>>(x, offs, weight, bias, down_w, up_w, scale,
                                (float*)d_out);
}

// round 16
// speedup vs baseline: 1.3064x; 1.3064x over previous
#include <cuda_runtime.h>

namespace {

constexpr int Bn = 2, Cin = 128, Co = 128, Hh = 128, Ww = 256;
constexpr int HW = Hh * Ww;
constexpr int KK = 9;
constexpr int Cmid = 32;
constexpr int TP = 32;          // pixels per block tile
constexpr int CC = 4;           // input channels per chunk
constexpr int NK = CC * KK;     // 36 (ci,k) pairs per chunk
constexpr int NCH = Cin / CC;   // 32 chunks

typedef unsigned long long ull;

__device__ __forceinline__ ull ffma2(ull a, ull b, ull c) {
  ull d;
  asm("fma.rn.f32x2 %0, %1, %2, %3;" : "=l"(d) : "l"(a), "l"(b), "l"(c));
  return d;
}
__device__ __forceinline__ ull pack2(float lo, float hi) {
  ull r;
  asm("mov.b64 %0, {%1, %2};" : "=l"(r) : "f"(lo), "f"(hi));
  return r;
}
__device__ __forceinline__ float2 unpack2(ull v) {
  float2 r;
  asm("mov.b64 {%0, %1}, %2;" : "=f"(r.x), "=f"(r.y) : "l"(v));
  return r;
}

struct SmemP1 {
  float wsm[NK][Co];   // 18432 B  weight slice, [cci*9+k][co]
  float sA[NK][TP];    //  4608 B  static conv column
  float sD[NK][TP];    //  4608 B  deformable column
};
struct SmemP2 {
  float hs[Co][TP];    // 16384 B  h (with bias)
  float ds[Co][TP];    // 16384 B  dx (with bias)
};
struct __align__(16) Smem {
  union { SmemP1 p1; SmemP2 p2; } u;  // 32768 B  (offset 0)
  int   midx[KK * TP][4];             //  4608 B  (offset 32768) bilinear corner idx
  float mw[KK * TP][4];               //  4608 B  (offset 37376) corner weights
  float los[Cmid][TP];                //  4096 B  (offset 41984) LoRA mid
};                                    // total 46080 B < 48KB static limit

}  // namespace

// transposed weight: g_wT[(ci*9+k)*128 + co]  (589 KB device scratch)
__device__ float g_wT[Cin * KK * Co];

__global__ void transpose_weight(const float* __restrict__ weight) {
  const int idx = blockIdx.x * blockDim.x + threadIdx.x;  // over Cin*KK*Co
  if (idx < Cin * KK * Co) {
    const int co = idx & 127;          // consecutive threads -> consecutive co
    const int cik = idx >> 7;          // ci*9 + k
    g_wT[idx] = weight[co * (Cin * KK) + cik];
  }
}

__global__ void __launch_bounds__(128, 4)
fused_dcn_lora(const float* __restrict__ x, const float* __restrict__ offs,
               const float* __restrict__ bias,
               const float* __restrict__ down_w, const float* __restrict__ up_w,
               const float* __restrict__ scale_p, float* __restrict__ out)
{
  __shared__ Smem s;
  const int tid = threadIdx.x;
  const int x0 = blockIdx.x * TP;
  const int y  = blockIdx.y;
  const int b  = blockIdx.z;
  const int cg = tid >> 2;    // 0..31  -> co0 = cg*4
  const int pg = tid & 3;     // 0..3   -> p0  = pg*8
  const int co0 = cg * 4;
  const int p0 = pg * 8;

  // ---- bilinear metadata per (k, p): 4 clamped corner indices + 4 weights ----
  for (int idx = tid; idx < KK * TP; idx += 128) {
    const int k = idx >> 5, p = idx & 31;
    const int ky = k / 3, kx = k - ky * 3;
    const float dy  = offs[(2 * k)     * HW + y * Ww + x0 + p];
    const float dxo = offs[(2 * k + 1) * HW + y * Ww + x0 + p];
    const float py = (float)(y - 1 + ky) + dy;
    const float px = (float)(x0 + p - 1 + kx) + dxo;
    const float fy0 = floorf(py), fx0 = floorf(px);
    const int iy0 = (int)fy0, ix0 = (int)fx0;
    const int iy1 = iy0 + 1,  ix1 = ix0 + 1;
    const float fy = py - fy0, fx = px - fx0;
    const bool vy0 = (iy0 >= 0) && (iy0 < Hh);
    const bool vy1 = (iy1 >= 0) && (iy1 < Hh);
    const bool vx0 = (ix0 >= 0) && (ix0 < Ww);
    const bool vx1 = (ix1 >= 0) && (ix1 < Ww);
    const int cy0 = ::min(::max(iy0, 0), Hh - 1);
    const int cy1 = ::min(::max(iy1, 0), Hh - 1);
    const int cx0 = ::min(::max(ix0, 0), Ww - 1);
    const int cx1 = ::min(::max(ix1, 0), Ww - 1);
    s.midx[idx][0] = cy0 * Ww + cx0;
    s.midx[idx][1] = cy0 * Ww + cx1;
    s.midx[idx][2] = cy1 * Ww + cx0;
    s.midx[idx][3] = cy1 * Ww + cx1;
    s.mw[idx][0] = (vy0 && vx0) ? (1.f - fy) * (1.f - fx) : 0.f;
    s.mw[idx][1] = (vy0 && vx1) ? (1.f - fy) * fx         : 0.f;
    s.mw[idx][2] = (vy1 && vx0) ? fy * (1.f - fx)         : 0.f;
    s.mw[idx][3] = (vy1 && vx1) ? fy * fx                 : 0.f;
  }
  __syncthreads();

  // ---- accumulators: [4 co][4 pixel-pairs] packed f32x2, for h and dx ----
  ull hacc[4][4], dacc[4][4];
#pragma unroll
  for (int i = 0; i < 4; i++)
#pragma unroll
    for (int q = 0; q < 4; q++) { hacc[i][q] = 0ull; dacc[i][q] = 0ull; }

  for (int ch = 0; ch < NCH; ch++) {
    const int ci0 = ch * CC;

    // stage weight slice from transposed layout: fully coalesced
    // slice = g_wT[(ci0*9 .. ci0*9+35)][co 0..127] = NK*Co floats
    {
      const float4* wt4 = (const float4*)(g_wT + ci0 * KK * Co);
#pragma unroll
      for (int it = 0; it < (NK * Co / 4) / 128; it++) {   // 9 iters
        const int i = it * 128 + tid;                      // float4 index in slice
        const float4 t = wt4[i];
        *(float4*)(&s.u.p1.wsm[i >> 5][(i & 31) * 4]) = t;
      }
    }

    // stage static + deformable columns for this chunk
#pragma unroll
    for (int it = 0; it < (NK * TP) / 128; it++) {
      const int idx = it * 128 + tid;
      const int kci = idx >> 5, p = idx & 31;
      const int cci = kci / KK, k = kci - cci * KK;
      const int ky = k / 3, kx = k - ky * 3;
      const float* plane = x + (size_t)(b * Cin + ci0 + cci) * HW;
      const int yy = y + ky - 1, xx = x0 + p + kx - 1;
      float v = 0.f;
      if (yy >= 0 && yy < Hh && xx >= 0 && xx < Ww) v = plane[yy * Ww + xx];
      s.u.p1.sA[kci][p] = v;
      const int km = k * TP + p;
      const int4   mi = *(const int4*)s.midx[km];
      const float4 mv = *(const float4*)s.mw[km];
      const float vd = mv.x * plane[mi.x] + mv.y * plane[mi.y]
                     + mv.z * plane[mi.z] + mv.w * plane[mi.w];
      s.u.p1.sD[kci][p] = vd;
    }
    __syncthreads();

    // MAC loop: per (ci,k): 1 LDS.128 weight, 4 LDS.128 acts, 32 FFMA2
#pragma unroll 6
    for (int kci = 0; kci < NK; kci++) {
      const float4 wv = *(const float4*)(&s.u.p1.wsm[kci][co0]);
      const ulonglong2* aA = (const ulonglong2*)(&s.u.p1.sA[kci][p0]);
      const ulonglong2* aD = (const ulonglong2*)(&s.u.p1.sD[kci][p0]);
      const ulonglong2 A0 = aA[0], A1 = aA[1];
      const ulonglong2 D0 = aD[0], D1 = aD[1];
      const ull a0 = A0.x, a1 = A0.y, a2 = A1.x, a3 = A1.y;
      const ull d0 = D0.x, d1 = D0.y, d2 = D1.x, d3 = D1.y;
#define MACROW(ic, wl) do {                                  \
      const ull wp = pack2((wl), (wl));                      \
      hacc[ic][0] = ffma2(wp, a0, hacc[ic][0]);              \
      hacc[ic][1] = ffma2(wp, a1, hacc[ic][1]);              \
      hacc[ic][2] = ffma2(wp, a2, hacc[ic][2]);              \
      hacc[ic][3] = ffma2(wp, a3, hacc[ic][3]);              \
      dacc[ic][0] = ffma2(wp, d0, dacc[ic][0]);              \
      dacc[ic][1] = ffma2(wp, d1, dacc[ic][1]);              \
      dacc[ic][2] = ffma2(wp, d2, dacc[ic][2]);              \
      dacc[ic][3] = ffma2(wp, d3, dacc[ic][3]);              \
    } while (0)
      MACROW(0, wv.x);
      MACROW(1, wv.y);
      MACROW(2, wv.z);
      MACROW(3, wv.w);
#undef MACROW
    }
    __syncthreads();
  }

  // ---- epilogue: bias, spill h/dx to smem (union overlay) ----
#pragma unroll
  for (int ic = 0; ic < 4; ic++) {
    const float bb = bias[co0 + ic];
#pragma unroll
    for (int q = 0; q < 4; q++) {
      const float2 th = unpack2(hacc[ic][q]);
      const float2 td = unpack2(dacc[ic][q]);
      s.u.p2.hs[co0 + ic][p0 + 2 * q]     = th.x + bb;
      s.u.p2.hs[co0 + ic][p0 + 2 * q + 1] = th.y + bb;
      s.u.p2.ds[co0 + ic][p0 + 2 * q]     = td.x + bb;
      s.u.p2.ds[co0 + ic][p0 + 2 * q + 1] = td.y + bb;
    }
  }
  __syncthreads();

  // ---- LoRA down: lo[m][p] = sum_c down_w[m][c]*dx[c][p] + down_w[m][128+c]*h[c][p]
  {
    const int m = tid >> 2;     // 32 mids x 4 pixel groups == 128 threads
    float lacc[8];
#pragma unroll
    for (int i = 0; i < 8; i++) lacc[i] = 0.f;
    const float* dwm = down_w + m * (2 * Co);
    for (int c = 0; c < Co; c++) {
      const float wd = dwm[c];
      const float wh = dwm[Co + c];
      const float* dr = &s.u.p2.ds[c][p0];
      const float* hr = &s.u.p2.hs[c][p0];
#pragma unroll
      for (int i = 0; i < 8; i++) lacc[i] += wd * dr[i] + wh * hr[i];
    }
#pragma unroll
    for (int i = 0; i < 8; i++) s.los[m][p0 + i] = lacc[i];
  }
  __syncthreads();

  // ---- LoRA up + residual + store ----
  const float sc = *scale_p;
#pragma unroll
  for (int ic = 0; ic < 4; ic++) {
    const int co = co0 + ic;
    float up[8];
#pragma unroll
    for (int i = 0; i < 8; i++) up[i] = 0.f;
    const float* uw = up_w + co * Cmid;
#pragma unroll
    for (int mm = 0; mm < Cmid; mm++) {
      const float wv2 = uw[mm];
      const float* lr = &s.los[mm][p0];
#pragma unroll
      for (int i = 0; i < 8; i++) up[i] += wv2 * lr[i];
    }
    const float* hr = &s.u.p2.hs[co][p0];
    float* og = out + (((size_t)b * Co + co) * Hh + y) * Ww + x0 + p0;
    float4 o0, o1;
    o0.x = hr[0] + sc * up[0];
    o0.y = hr[1] + sc * up[1];
    o0.z = hr[2] + sc * up[2];
    o0.w = hr[3] + sc * up[3];
    o1.x = hr[4] + sc * up[4];
    o1.y = hr[5] + sc * up[5];
    o1.z = hr[6] + sc * up[6];
    o1.w = hr[7] + sc * up[7];
    *(float4*)og       = o0;
    *(float4*)(og + 4) = o1;
  }
}

extern "C" void kernel_launch(void* const* d_in, const int* in_sizes, int n_in,
                              void* d_out, int out_size) {
  (void)in_sizes; (void)n_in; (void)out_size;
  const float* x      = (const float*)d_in[0];
  const float* offs   = (const float*)d_in[1];
  const float* weight = (const float*)d_in[2];
  const float* bias   = (const float*)d_in[3];
  const float* down_w = (const float*)d_in[4];
  const float* up_w   = (const float*)d_in[5];
  const float* scale  = (const float*)d_in[6];

  // 1) transpose weight into g_wT (deterministic, graph-capturable)
  const int nW = Cin * KK * Co;
  transpose_weight<<<(nW + 255) / 256, 256>>>(weight);

  // 2) fused main kernel
  dim3 grid(Ww / TP, Hh, Bn);   // 8 x 128 x 2 = 2048 blocks
  fused_dcn_lora<<<grid, 128>>>(x, offs, bias, down_w, up_w, scale,
                                (float*)d_out);
}